// round 8
// baseline (speedup 1.0000x reference)
#include <cuda_runtime.h>

// Problem dims (fixed)
#define Bc  4
#define Sc  2048
#define Ec  1024
#define Hc  16
#define Dc  64
#define HDc (Hc * Dc)      // 1024
#define Mc  (Bc * Sc)      // 8192

// Scratch
__device__ float g_Q[Bc * Hc * Sc * Dc];
__device__ float g_K[Bc * Hc * Sc * Dc];
__device__ float g_V[Bc * Hc * Sc * Dc];
__device__ float g_Vt[Bc * Hc * Dc * Sc];    // V transposed [bh][d][s]
__device__ float g_AO[Bc * Sc * HDc];        // tf32-rounded by flash epilogue
// tf32-pre-rounded inputs (prepass)
__device__ float g_xr [Mc * Ec];
__device__ float g_Wqt[Hc * Dc * Ec];        // transposed: [h][d][e]
__device__ float g_Wkt[Hc * Dc * Ec];
__device__ float g_Wvt[Hc * Dc * Ec];
__device__ float g_Wot[Ec * HDc];            // transposed: [n][k]

// ---------------------------------------------------------------------------
// helpers
// ---------------------------------------------------------------------------
__device__ __forceinline__ unsigned f2tf32(float x) {
    unsigned r;
    asm("cvt.rna.tf32.f32 %0, %1;" : "=r"(r) : "f"(x));
    return r;
}
__device__ __forceinline__ float tf32r(float x) { return __uint_as_float(f2tf32(x)); }

__device__ __forceinline__ void mma8(float* d, const unsigned* a, unsigned b0, unsigned b1) {
    asm volatile(
        "mma.sync.aligned.m16n8k8.row.col.f32.tf32.tf32.f32 "
        "{%0,%1,%2,%3}, {%4,%5,%6,%7}, {%8,%9}, {%0,%1,%2,%3};"
        : "+f"(d[0]), "+f"(d[1]), "+f"(d[2]), "+f"(d[3])
        : "r"(a[0]), "r"(a[1]), "r"(a[2]), "r"(a[3]), "r"(b0), "r"(b1));
}

// ldmatrix x4 on tf32 data: each b16-pair = one tf32 word. Byte address in
// shared space; lane L supplies row (L&15) of matrix pair, (L>>4) selects
// the +4-col half. Yields exact mma.sync tf32 fragment layout.
__device__ __forceinline__ void ldsm4(unsigned* f, unsigned saddr_bytes) {
    asm volatile("ldmatrix.sync.aligned.m8n8.x4.shared.b16 {%0,%1,%2,%3}, [%4];"
        : "=r"(f[0]), "=r"(f[1]), "=r"(f[2]), "=r"(f[3]) : "r"(saddr_bytes));
}

__device__ __forceinline__ void cp16(void* smem, const void* g) {
    unsigned sa = (unsigned)__cvta_generic_to_shared(smem);
    asm volatile("cp.async.cg.shared.global [%0], [%1], 16;" :: "r"(sa), "l"(g));
}
#define CP_COMMIT asm volatile("cp.async.commit_group;")
#define CP_WAIT0  asm volatile("cp.async.wait_group 0;")

// ---------------------------------------------------------------------------
// Prepass A: RNA-round x -> g_xr (grid-stride float4).
// ---------------------------------------------------------------------------
__global__ __launch_bounds__(256) void round_x_kernel(const float* __restrict__ x)
{
    const float4* src = (const float4*)x;
    float4* dst = (float4*)g_xr;
    const int n4 = Mc * Ec / 4;
    for (int i = blockIdx.x * blockDim.x + threadIdx.x; i < n4;
         i += gridDim.x * blockDim.x) {
        float4 v = src[i];
        dst[i] = make_float4(tf32r(v.x), tf32r(v.y), tf32r(v.z), tf32r(v.w));
    }
}

// ---------------------------------------------------------------------------
// Prepass B: batched tiled transpose + tf32 round.
// SEL 0/1/2: Wq/Wk/Wv [h][E][D] -> g_W?t [h][D][E]   (R=E, C=D, batch=H)
// SEL 3:     Wo [K][N] -> g_Wot [N][K]               (R=HDc, C=Ec, batch=1)
// SEL 4:     g_V [bh][S][D] -> g_Vt [bh][D][S]       (R=S, C=D, batch=64)
// ---------------------------------------------------------------------------
template<int SEL>
__global__ __launch_bounds__(256) void transpose_round_kernel(const float* __restrict__ srcp)
{
    __shared__ float t[32][33];
    int R, C; const float* src; float* dst;
    if      (SEL == 0) { src = srcp; dst = g_Wqt; R = Ec;  C = Dc; }
    else if (SEL == 1) { src = srcp; dst = g_Wkt; R = Ec;  C = Dc; }
    else if (SEL == 2) { src = srcp; dst = g_Wvt; R = Ec;  C = Dc; }
    else if (SEL == 3) { src = srcp; dst = g_Wot; R = HDc; C = Ec; }
    else               { src = g_V;  dst = g_Vt;  R = Sc;  C = Dc; }

    size_t off = (size_t)blockIdx.z * R * C;
    const float* S = src + off;
    float* D = dst + off;
    int c0 = blockIdx.x * 32, r0 = blockIdx.y * 32;
    int tx = threadIdx.x & 31, ty = threadIdx.x >> 5;   // 32 x 8
#pragma unroll
    for (int i = 0; i < 32; i += 8)
        t[ty + i][tx] = S[(size_t)(r0 + ty + i) * C + c0 + tx];
    __syncthreads();
#pragma unroll
    for (int i = 0; i < 32; i += 8)
        D[(size_t)(c0 + ty + i) * R + r0 + tx] = tf32r(t[tx][ty + i]);
}

// ---------------------------------------------------------------------------
// Kernel 1: FUSED QKV projection. Block 128(M) x 192(N=Q|K|V of one head)
// x 32(K). 256 thr = 8 warps (4m x 2n), warp tile 32x96. LDSM fragments.
// smem (u32): As0@0 As1@4608 (128x36) | Bs0@9216 Bs1@16128 (192x36, n-major)
// ---------------------------------------------------------------------------
#define QKV_AS(buf) ((buf) * 4608)
#define QKV_BS(buf) (9216 + (buf) * 6912)
#define QKV_SMEM_BYTES (23040 * 4)

__global__ __launch_bounds__(256, 1) void qkv_fused_kernel(
    const float* __restrict__ bq, const float* __restrict__ bk,
    const float* __restrict__ bv)
{
    extern __shared__ __align__(16) unsigned smq[];
    const unsigned sbase = (unsigned)__cvta_generic_to_shared(smq);

    const int tid  = threadIdx.x;
    const int warp = tid >> 5, lane = tid & 31;
    const int wm = warp >> 1, wn = warp & 1;
    const int r = lane >> 2, c = lane & 3;
    const int ln15 = lane & 15, lhi4 = (lane >> 4) * 4;
    const int m0 = blockIdx.x * 128;
    const int h  = blockIdx.y;

    const float* __restrict__ Wt[3] = {
        g_Wqt + (size_t)h * Dc * Ec,
        g_Wkt + (size_t)h * Dc * Ec,
        g_Wvt + (size_t)h * Dc * Ec };
    const float* __restrict__ xr = g_xr;

    // stage tile 0
#pragma unroll
    for (int it = 0; it < 4; it++) {
        int i = tid + it * 256; int m = i >> 3; int seg = (i & 7) * 4;
        cp16(&smq[QKV_AS(0) + m * 36 + seg], xr + (size_t)(m0 + m) * Ec + seg);
    }
#pragma unroll
    for (int it = 0; it < 6; it++) {
        int i = tid + it * 256; int row = i >> 3; int seg = (i & 7) * 4;
        cp16(&smq[QKV_BS(0) + row * 36 + seg],
             Wt[row >> 6] + (size_t)(row & 63) * Ec + seg);
    }
    CP_COMMIT;

    float acc[2][12][4];
#pragma unroll
    for (int mt = 0; mt < 2; mt++)
#pragma unroll
        for (int nt = 0; nt < 12; nt++)
#pragma unroll
            for (int j = 0; j < 4; j++) acc[mt][nt][j] = 0.0f;

    // per-thread LDSM base offsets (u32 units)
    const int aOff = (wm * 32 + ln15) * 36 + lhi4;     // + mt*16*36 + kk*8
    const int bOff = (wn * 96 + ln15) * 36 + lhi4;     // + p*16*36 + kk*8

    int buf = 0;
    for (int k0 = 0; k0 < Ec; k0 += 32, buf ^= 1) {
        CP_WAIT0;
        __syncthreads();

        if (k0 + 32 < Ec) {
            int nb = buf ^ 1;
#pragma unroll
            for (int it = 0; it < 4; it++) {
                int i = tid + it * 256; int m = i >> 3; int seg = (i & 7) * 4;
                cp16(&smq[QKV_AS(nb) + m * 36 + seg],
                     xr + (size_t)(m0 + m) * Ec + k0 + 32 + seg);
            }
#pragma unroll
            for (int it = 0; it < 6; it++) {
                int i = tid + it * 256; int row = i >> 3; int seg = (i & 7) * 4;
                cp16(&smq[QKV_BS(nb) + row * 36 + seg],
                     Wt[row >> 6] + (size_t)(row & 63) * Ec + k0 + 32 + seg);
            }
            CP_COMMIT;
        }

        const unsigned aB = sbase + 4 * (QKV_AS(buf) + aOff);
        const unsigned bB = sbase + 4 * (QKV_BS(buf) + bOff);
#pragma unroll
        for (int kk = 0; kk < 4; kk++) {
            unsigned af[2][4], bf[6][4];
#pragma unroll
            for (int mt = 0; mt < 2; mt++)
                ldsm4(af[mt], aB + 4 * (mt * 16 * 36 + kk * 8));
#pragma unroll
            for (int p = 0; p < 6; p++)
                ldsm4(bf[p], bB + 4 * (p * 16 * 36 + kk * 8));
#pragma unroll
            for (int nt = 0; nt < 12; nt++) {
                unsigned b0 = bf[nt >> 1][nt & 1];
                unsigned b1 = bf[nt >> 1][2 + (nt & 1)];
#pragma unroll
                for (int mt = 0; mt < 2; mt++)
                    mma8(acc[mt][nt], af[mt], b0, b1);
            }
        }
    }

    // epilogue: scatter Q/K/V to [B,H,S,D], tf32-round
    const int bI = m0 >> 11;
    const int sBase = m0 & 2047;
#pragma unroll
    for (int nt = 0; nt < 12; nt++) {
        int g   = wn * 96 + nt * 8;
        int mat = g >> 6;
        int d   = (g & 63) + 2 * c;
        float* Out = (mat == 0) ? g_Q : (mat == 1) ? g_K : g_V;
        const float* bias = (mat == 0) ? bq : (mat == 1) ? bk : bv;
        float bb0 = bias[h * Dc + d], bb1 = bias[h * Dc + d + 1];
#pragma unroll
        for (int mt = 0; mt < 2; mt++) {
            int lr = wm * 32 + mt * 16 + r;
            size_t base = ((((size_t)bI * Hc + h) * Sc) + sBase + lr) * Dc + d;
            *(float2*)(Out + base) =
                make_float2(tf32r(acc[mt][nt][0] + bb0), tf32r(acc[mt][nt][1] + bb1));
            *(float2*)(Out + base + 8 * Dc) =
                make_float2(tf32r(acc[mt][nt][2] + bb0), tf32r(acc[mt][nt][3] + bb1));
        }
    }
}

// ---------------------------------------------------------------------------
// Kernel 3: output projection. Block 128(M) x 128(N) x 32(K). 256 thr =
// 8 warps (4m x 2n), warp tile 32x64. LDSM fragments; B = g_Wot (n-major).
// smem (u32): As0@0 As1@4608 | Bs0@9216 Bs1@13824 (128x36) = 18432 u32
// ---------------------------------------------------------------------------
#define O_AS(buf) ((buf) * 4608)
#define O_BS(buf) (9216 + (buf) * 4608)
#define O_SMEM_BYTES (18432 * 4)

__global__ __launch_bounds__(256, 1) void out_gemm_kernel(
    const float* __restrict__ bo, float* __restrict__ outp)
{
    extern __shared__ __align__(16) unsigned smo[];
    const unsigned sbase = (unsigned)__cvta_generic_to_shared(smo);

    const float* __restrict__ A = (const float*)g_AO;
    const float* __restrict__ B = (const float*)g_Wot;

    const int tid  = threadIdx.x;
    const int warp = tid >> 5, lane = tid & 31;
    const int wm = warp >> 1, wn = warp & 1;
    const int r = lane >> 2, c = lane & 3;
    const int ln15 = lane & 15, lhi4 = (lane >> 4) * 4;
    const int m0 = blockIdx.y * 128;
    const int ncol0 = blockIdx.x * 128;

#pragma unroll
    for (int it = 0; it < 4; it++) {
        int i = tid + it * 256; int m = i >> 3; int seg = (i & 7) * 4;
        cp16(&smo[O_AS(0) + m * 36 + seg], A + (size_t)(m0 + m) * HDc + seg);
    }
#pragma unroll
    for (int it = 0; it < 4; it++) {
        int i = tid + it * 256; int row = i >> 3; int seg = (i & 7) * 4;
        cp16(&smo[O_BS(0) + row * 36 + seg],
             B + (size_t)(ncol0 + row) * HDc + seg);
    }
    CP_COMMIT;

    float acc[2][8][4];
#pragma unroll
    for (int mt = 0; mt < 2; mt++)
#pragma unroll
        for (int nt = 0; nt < 8; nt++)
#pragma unroll
            for (int j = 0; j < 4; j++) acc[mt][nt][j] = 0.0f;

    const int aOff = (wm * 32 + ln15) * 36 + lhi4;
    const int bOff = (wn * 64 + ln15) * 36 + lhi4;

    int buf = 0;
    for (int k0 = 0; k0 < HDc; k0 += 32, buf ^= 1) {
        CP_WAIT0;
        __syncthreads();

        if (k0 + 32 < HDc) {
            int nb = buf ^ 1;
#pragma unroll
            for (int it = 0; it < 4; it++) {
                int i = tid + it * 256; int m = i >> 3; int seg = (i & 7) * 4;
                cp16(&smo[O_AS(nb) + m * 36 + seg],
                     A + (size_t)(m0 + m) * HDc + k0 + 32 + seg);
            }
#pragma unroll
            for (int it = 0; it < 4; it++) {
                int i = tid + it * 256; int row = i >> 3; int seg = (i & 7) * 4;
                cp16(&smo[O_BS(nb) + row * 36 + seg],
                     B + (size_t)(ncol0 + row) * HDc + k0 + 32 + seg);
            }
            CP_COMMIT;
        }

        const unsigned aB = sbase + 4 * (O_AS(buf) + aOff);
        const unsigned bB = sbase + 4 * (O_BS(buf) + bOff);
#pragma unroll
        for (int kk = 0; kk < 4; kk++) {
            unsigned af[2][4], bf[4][4];
#pragma unroll
            for (int mt = 0; mt < 2; mt++)
                ldsm4(af[mt], aB + 4 * (mt * 16 * 36 + kk * 8));
#pragma unroll
            for (int p = 0; p < 4; p++)
                ldsm4(bf[p], bB + 4 * (p * 16 * 36 + kk * 8));
#pragma unroll
            for (int nt = 0; nt < 8; nt++) {
                unsigned b0 = bf[nt >> 1][nt & 1];
                unsigned b1 = bf[nt >> 1][2 + (nt & 1)];
#pragma unroll
                for (int mt = 0; mt < 2; mt++)
                    mma8(acc[mt][nt], af[mt], b0, b1);
            }
        }
    }

#pragma unroll
    for (int mt = 0; mt < 2; mt++) {
        int mrow = m0 + wm * 32 + mt * 16 + r;
#pragma unroll
        for (int nt = 0; nt < 8; nt++) {
            int d = ncol0 + wn * 64 + nt * 8 + 2 * c;
            float bb0 = bo[d], bb1 = bo[d + 1];
            *(float2*)(outp + (size_t)mrow * Ec + d) =
                make_float2(acc[mt][nt][0] + bb0, acc[mt][nt][1] + bb1);
            *(float2*)(outp + (size_t)(mrow + 8) * Ec + d) =
                make_float2(acc[mt][nt][2] + bb0, acc[mt][nt][3] + bb1);
        }
    }
}

// ---------------------------------------------------------------------------
// Kernel 2: flash attention. BQ=128 (8 warps), BKT=64, D=64, occ 2.
// K staged [token][d] (QK^T B-frags via LDSM directly); V staged from g_Vt
// [d][token] (PV B-frags via LDSM); P-frags via LDSM. Causal early-out.
// smem (u32): Ks0@0 Vt0@4352 | Ks1@8704 Vt1@13056 (each 64x68)
//             Ps@17408 + warp*1088 (16x68) x8 -> 26112 u32 = 104448 B
// ---------------------------------------------------------------------------
#define PS_LD   68
#define PS_BASE 17408
#define F_SMEM_BYTES (26112 * 4)

__device__ __forceinline__ void stage_kv(unsigned* Ksb, unsigned* Vsb,
                                         const float* Kb, const float* Vtb,
                                         int k0, int tid)
{
#pragma unroll
    for (int it = 0; it < 4; it++) {
        int i = tid + it * 256;
        int row = i >> 4;
        int seg = (i & 15) * 4;
        cp16(&Ksb[row * 68 + seg], Kb  + (size_t)(k0 + row) * Dc + seg);
        cp16(&Vsb[row * 68 + seg], Vtb + (size_t)row * Sc + k0 + seg);
    }
}

__global__ __launch_bounds__(256, 2) void flash_tf32_kernel()
{
    extern __shared__ __align__(16) unsigned sm[];
    const unsigned sbase = (unsigned)__cvta_generic_to_shared(sm);

    const int bh = blockIdx.y;
    const int b  = bh >> 4, h = bh & 15;
    const int q0 = blockIdx.x * 128;

    const float* __restrict__ Qb  = g_Q  + (size_t)bh * Sc * Dc;
    const float* __restrict__ Kb  = g_K  + (size_t)bh * Sc * Dc;
    const float* __restrict__ Vtb = g_Vt + (size_t)bh * Dc * Sc;

    const int tid  = threadIdx.x;
    const int warp = tid >> 5, lane = tid & 31;
    const int r = lane >> 2, c = lane & 3;
    const int ln15 = lane & 15, lhi4 = (lane >> 4) * 4;

    // stage Q (128x64) transiently in buf0 region, extract A-fragments
#pragma unroll
    for (int it = 0; it < 8; it++) {
        int i = tid + it * 256;
        int row = i >> 4, seg = (i & 15) * 4;
        *(uint4*)&sm[row * 68 + seg] = *(const uint4*)(Qb + (size_t)(q0 + row) * Dc + seg);
    }
    __syncthreads();
    unsigned qf[8][4];
    {
        const unsigned qB = sbase + 4 * ((warp * 16 + ln15) * 68 + lhi4);
#pragma unroll
        for (int kk = 0; kk < 8; kk++)
            ldsm4(qf[kk], qB + 4 * (kk * 8));
    }
    __syncthreads();

    unsigned* Ps = sm + PS_BASE + warp * (16 * PS_LD);
    const unsigned psB = sbase + 4 * (PS_BASE + warp * (16 * PS_LD) + ln15 * PS_LD + lhi4);

    const int nkt = 2 * (blockIdx.x + 1);
    stage_kv(sm, sm + 4352, Kb, Vtb, 0, tid);
    CP_COMMIT;

    float of[8][4];
#pragma unroll
    for (int nt = 0; nt < 8; nt++)
#pragma unroll
        for (int j = 0; j < 4; j++) of[nt][j] = 0.0f;
    float m_lo = -1e30f, m_hi = -1e30f, l_lo = 0.0f, l_hi = 0.0f;

    const int qlo = q0 + warp * 16 + r;
    const int qhi = qlo + 8;
    const int qmax = q0 + warp * 16 + 15;

    const int fOff = ln15 * 68 + lhi4;   // lane part of K/V ldsm offsets

    int buf = 0;
    for (int kt = 0; kt < nkt; kt++) {
        CP_WAIT0;
        __syncthreads();
        if (kt + 1 < nkt) {
            int nb = buf ^ 1;
            stage_kv(sm + nb * 8704, sm + nb * 8704 + 4352, Kb, Vtb, (kt + 1) * 64, tid);
            CP_COMMIT;
        }
        const int kbase = kt * 64;
        if (kbase <= qmax) {
            const unsigned kB = sbase + 4 * (buf * 8704 + fOff);
            const unsigned vB = sbase + 4 * (buf * 8704 + 4352 + fOff);

            // S = Q K^T
            float sf[8][4];
#pragma unroll
            for (int nt = 0; nt < 8; nt++)
                sf[nt][0] = sf[nt][1] = sf[nt][2] = sf[nt][3] = 0.0f;
#pragma unroll
            for (int kk = 0; kk < 8; kk++) {
                unsigned kf[4][4];
#pragma unroll
                for (int p = 0; p < 4; p++)
                    ldsm4(kf[p], kB + 4 * (p * 16 * 68 + kk * 8));
#pragma unroll
                for (int nt = 0; nt < 8; nt++)
                    mma8(sf[nt], qf[kk], kf[nt >> 1][nt & 1], kf[nt >> 1][2 + (nt & 1)]);
            }

            // scale + causal mask + online softmax
            float mx_lo = -1e30f, mx_hi = -1e30f;
#pragma unroll
            for (int nt = 0; nt < 8; nt++) {
                int kg0 = kbase + nt * 8 + 2 * c;
                int kg1 = kg0 + 1;
                float s0 = sf[nt][0] * 0.125f; if (kg0 > qlo) s0 = -1e30f;
                float s1 = sf[nt][1] * 0.125f; if (kg1 > qlo) s1 = -1e30f;
                float s2 = sf[nt][2] * 0.125f; if (kg0 > qhi) s2 = -1e30f;
                float s3 = sf[nt][3] * 0.125f; if (kg1 > qhi) s3 = -1e30f;
                sf[nt][0] = s0; sf[nt][1] = s1; sf[nt][2] = s2; sf[nt][3] = s3;
                mx_lo = fmaxf(mx_lo, fmaxf(s0, s1));
                mx_hi = fmaxf(mx_hi, fmaxf(s2, s3));
            }
            mx_lo = fmaxf(mx_lo, __shfl_xor_sync(0xffffffffu, mx_lo, 1));
            mx_lo = fmaxf(mx_lo, __shfl_xor_sync(0xffffffffu, mx_lo, 2));
            mx_hi = fmaxf(mx_hi, __shfl_xor_sync(0xffffffffu, mx_hi, 1));
            mx_hi = fmaxf(mx_hi, __shfl_xor_sync(0xffffffffu, mx_hi, 2));

            float mn_lo = fmaxf(m_lo, mx_lo), mn_hi = fmaxf(m_hi, mx_hi);
            float a_lo = __expf(m_lo - mn_lo), a_hi = __expf(m_hi - mn_hi);

            float ps_lo = 0.0f, ps_hi = 0.0f;
#pragma unroll
            for (int nt = 0; nt < 8; nt++) {
                float p0 = __expf(sf[nt][0] - mn_lo);
                float p1 = __expf(sf[nt][1] - mn_lo);
                float p2 = __expf(sf[nt][2] - mn_hi);
                float p3 = __expf(sf[nt][3] - mn_hi);
                ps_lo += p0 + p1;  ps_hi += p2 + p3;
                *(uint2*)&Ps[r * PS_LD + nt * 8 + 2 * c]       = make_uint2(f2tf32(p0), f2tf32(p1));
                *(uint2*)&Ps[(r + 8) * PS_LD + nt * 8 + 2 * c] = make_uint2(f2tf32(p2), f2tf32(p3));
            }
            ps_lo += __shfl_xor_sync(0xffffffffu, ps_lo, 1);
            ps_lo += __shfl_xor_sync(0xffffffffu, ps_lo, 2);
            ps_hi += __shfl_xor_sync(0xffffffffu, ps_hi, 1);
            ps_hi += __shfl_xor_sync(0xffffffffu, ps_hi, 2);
            l_lo = l_lo * a_lo + ps_lo;
            l_hi = l_hi * a_hi + ps_hi;
            m_lo = mn_lo; m_hi = mn_hi;

#pragma unroll
            for (int nt = 0; nt < 8; nt++) {
                of[nt][0] *= a_lo; of[nt][1] *= a_lo;
                of[nt][2] *= a_hi; of[nt][3] *= a_hi;
            }
            __syncwarp();

            // O += P V  (V-frags from transposed V tile via LDSM)
#pragma unroll
            for (int kk = 0; kk < 8; kk++) {
                unsigned pf[4], vf[4][4];
                ldsm4(pf, psB + 4 * (kk * 8));
#pragma unroll
                for (int p = 0; p < 4; p++)
                    ldsm4(vf[p], vB + 4 * (p * 16 * 68 + kk * 8));
#pragma unroll
                for (int nt = 0; nt < 8; nt++)
                    mma8(of[nt], pf, vf[nt >> 1][nt & 1], vf[nt >> 1][2 + (nt & 1)]);
            }
        }
        buf ^= 1;
    }

    // epilogue: normalize, tf32-round, write AO [B,S,H*D]
    float il_lo = 1.0f / l_lo, il_hi = 1.0f / l_hi;
    size_t rb_lo = ((size_t)b * Sc + qlo) * HDc + h * Dc;
    size_t rb_hi = ((size_t)b * Sc + qhi) * HDc + h * Dc;
#pragma unroll
    for (int nt = 0; nt < 8; nt++) {
        int d = nt * 8 + 2 * c;
        *(float2*)(g_AO + rb_lo + d) =
            make_float2(tf32r(of[nt][0] * il_lo), tf32r(of[nt][1] * il_lo));
        *(float2*)(g_AO + rb_hi + d) =
            make_float2(tf32r(of[nt][2] * il_hi), tf32r(of[nt][3] * il_hi));
    }
}

// ---------------------------------------------------------------------------
extern "C" void kernel_launch(void* const* d_in, const int* in_sizes, int n_in,
                              void* d_out, int out_size)
{
    const float* x  = (const float*)d_in[0];
    const float* Wq = (const float*)d_in[1];
    const float* bq = (const float*)d_in[2];
    const float* Wk = (const float*)d_in[3];
    const float* bk = (const float*)d_in[4];
    const float* Wv = (const float*)d_in[5];
    const float* bv = (const float*)d_in[6];
    const float* Wo = (const float*)d_in[7];
    const float* bo = (const float*)d_in[8];
    float* out = (float*)d_out;

    cudaFuncSetAttribute(qkv_fused_kernel,
                         cudaFuncAttributeMaxDynamicSharedMemorySize, QKV_SMEM_BYTES);
    cudaFuncSetAttribute(flash_tf32_kernel,
                         cudaFuncAttributeMaxDynamicSharedMemorySize, F_SMEM_BYTES);
    cudaFuncSetAttribute(out_gemm_kernel,
                         cudaFuncAttributeMaxDynamicSharedMemorySize, O_SMEM_BYTES);

    round_x_kernel<<<1024, 256>>>(x);
    transpose_round_kernel<0><<<dim3(Dc / 32, Ec / 32, Hc), 256>>>(Wq);
    transpose_round_kernel<1><<<dim3(Dc / 32, Ec / 32, Hc), 256>>>(Wk);
    transpose_round_kernel<2><<<dim3(Dc / 32, Ec / 32, Hc), 256>>>(Wv);
    transpose_round_kernel<3><<<dim3(Ec / 32, HDc / 32, 1), 256>>>(Wo);

    dim3 g1(Mc / 128, Hc);
    qkv_fused_kernel<<<g1, 256, QKV_SMEM_BYTES>>>(bq, bk, bv);

    // V -> Vt (after QKV writes g_V)
    transpose_round_kernel<4><<<dim3(Dc / 32, Sc / 32, Bc * Hc), 256>>>(nullptr);

    dim3 g2(Sc / 128, Bc * Hc);
    flash_tf32_kernel<<<g2, 256, F_SMEM_BYTES>>>();

    dim3 g3(Ec / 128, Mc / 128);
    out_gemm_kernel<<<g3, 256, O_SMEM_BYTES>>>(bo, out);
}

// round 10
// speedup vs baseline: 1.8938x; 1.8938x over previous
#include <cuda_runtime.h>
#include <cuda_fp16.h>
#include <cstdint>

// Problem dims (fixed)
#define Bc  4
#define Sc  2048
#define Ec  1024
#define Hc  16
#define Dc  64
#define HDc (Hc * Dc)      // 1024
#define Mc  (Bc * Sc)      // 8192

// Scratch (fp16 pipeline)
__device__ __half g_Qh[Bc * Hc * Sc * Dc];
__device__ __half g_Kh[Bc * Hc * Sc * Dc];
__device__ __half g_Vh[Bc * Hc * Sc * Dc];
__device__ __half g_AOh[Bc * Sc * HDc];
__device__ __half g_xh [Mc * Ec];
__device__ __half g_Wqt[Hc * Dc * Ec];   // transposed [h][d][e]
__device__ __half g_Wkt[Hc * Dc * Ec];
__device__ __half g_Wvt[Hc * Dc * Ec];
__device__ __half g_Wot[Ec * HDc];       // transposed [n][k]

// ---------------------------------------------------------------------------
// helpers
// ---------------------------------------------------------------------------
__device__ __forceinline__ unsigned pk(float a, float b) {
    __half2 h = __floats2half2_rn(a, b);
    return *reinterpret_cast<unsigned*>(&h);
}

__device__ __forceinline__ void mma16(float* d, const unsigned* a, unsigned b0, unsigned b1) {
    asm volatile(
        "mma.sync.aligned.m16n8k16.row.col.f32.f16.f16.f32 "
        "{%0,%1,%2,%3}, {%4,%5,%6,%7}, {%8,%9}, {%0,%1,%2,%3};"
        : "+f"(d[0]), "+f"(d[1]), "+f"(d[2]), "+f"(d[3])
        : "r"(a[0]), "r"(a[1]), "r"(a[2]), "r"(a[3]), "r"(b0), "r"(b1));
}

__device__ __forceinline__ void ldsm4t(unsigned* f, unsigned addr_bytes) {
    asm volatile("ldmatrix.sync.aligned.m8n8.x4.trans.shared.b16 {%0,%1,%2,%3}, [%4];"
        : "=r"(f[0]), "=r"(f[1]), "=r"(f[2]), "=r"(f[3]) : "r"(addr_bytes));
}

__device__ __forceinline__ void cp16(void* smem, const void* g) {
    unsigned sa = (unsigned)__cvta_generic_to_shared(smem);
    asm volatile("cp.async.cg.shared.global [%0], [%1], 16;" :: "r"(sa), "l"(g));
}
#define CP_COMMIT asm volatile("cp.async.commit_group;")
#define CP_WAIT0  asm volatile("cp.async.wait_group 0;")

// ---------------------------------------------------------------------------
// Prepass A: x (fp32) -> g_xh (fp16)
// ---------------------------------------------------------------------------
__global__ __launch_bounds__(256) void round_x_kernel(const float* __restrict__ x)
{
    const float4* src = (const float4*)x;
    uint2* dst = (uint2*)g_xh;
    const int n4 = Mc * Ec / 4;
    for (int i = blockIdx.x * blockDim.x + threadIdx.x; i < n4;
         i += gridDim.x * blockDim.x) {
        float4 v = src[i];
        dst[i] = make_uint2(pk(v.x, v.y), pk(v.z, v.w));
    }
}

// ---------------------------------------------------------------------------
// Prepass B: batched tiled transpose + fp16 convert (weights).
// SEL 0/1/2: Wq/Wk/Wv [h][E][D] -> [h][D][E];  SEL 3: Wo [HD][E] -> [E][HD]
// ---------------------------------------------------------------------------
template<int SEL>
__global__ __launch_bounds__(256) void transpose_half_kernel(const float* __restrict__ srcp)
{
    __shared__ float t[32][33];
    int R, C; __half* dst;
    if      (SEL == 0) { dst = g_Wqt; R = Ec;  C = Dc; }
    else if (SEL == 1) { dst = g_Wkt; R = Ec;  C = Dc; }
    else if (SEL == 2) { dst = g_Wvt; R = Ec;  C = Dc; }
    else               { dst = g_Wot; R = HDc; C = Ec; }

    size_t off = (size_t)blockIdx.z * R * C;
    const float* S = srcp + off;
    __half* D = dst + off;
    int c0 = blockIdx.x * 32, r0 = blockIdx.y * 32;
    int tx = threadIdx.x & 31, ty = threadIdx.x >> 5;
#pragma unroll
    for (int i = 0; i < 32; i += 8)
        t[ty + i][tx] = S[(size_t)(r0 + ty + i) * C + c0 + tx];
    __syncthreads();
#pragma unroll
    for (int i = 0; i < 32; i += 8)
        D[(size_t)(c0 + ty + i) * R + r0 + tx] = __float2half_rn(t[tx][ty + i]);
}

// ---------------------------------------------------------------------------
// Kernel 1: FUSED QKV projection (fp16 HMMA k16).
// Block 128(M) x 192(N = Q|K|V of one head) x 64(K halves). 256 thr = 8 warps
// (4m x 2n), warp tile 32x96. Rows: 64 halves = 32 b32, stride 36 b32 (144 B)
// -> fragment LDS bank = 4r+c = lane (conflict-free).
// smem bytes: A0@0 A1@18432 | B0@36864 B1@64512  -> 92160 B
// ---------------------------------------------------------------------------
#define QKV_A(b) ((b) * 18432)
#define QKV_B(b) (36864 + (b) * 27648)
#define QKV_SMEM 92160

__global__ __launch_bounds__(256, 1) void qkv_fp16_kernel(
    const float* __restrict__ bq, const float* __restrict__ bk,
    const float* __restrict__ bv)
{
    extern __shared__ __align__(16) char smq[];

    const int tid  = threadIdx.x;
    const int warp = tid >> 5, lane = tid & 31;
    const int wm = warp >> 1, wn = warp & 1;
    const int r = lane >> 2, c = lane & 3;
    const int m0 = blockIdx.x * 128;
    const int h  = blockIdx.y;

    const __half* __restrict__ W0 = g_Wqt + (size_t)h * Dc * Ec;
    const __half* __restrict__ W1 = g_Wkt + (size_t)h * Dc * Ec;
    const __half* __restrict__ W2 = g_Wvt + (size_t)h * Dc * Ec;
    const __half* __restrict__ xh = g_xh;

    // stage tile 0
#pragma unroll
    for (int it = 0; it < 4; it++) {
        int i = tid + it * 256; int m = i >> 3; int ch = i & 7;
        cp16(smq + QKV_A(0) + m * 144 + ch * 16, xh + (size_t)(m0 + m) * Ec + ch * 8);
    }
#pragma unroll
    for (int it = 0; it < 6; it++) {
        int i = tid + it * 256; int row = i >> 3; int ch = i & 7;
        const __half* w = (row < 64) ? W0 : (row < 128) ? W1 : W2;
        cp16(smq + QKV_B(0) + row * 144 + ch * 16, w + (size_t)(row & 63) * Ec + ch * 8);
    }
    CP_COMMIT;

    float acc[2][12][4];
#pragma unroll
    for (int mt = 0; mt < 2; mt++)
#pragma unroll
        for (int nt = 0; nt < 12; nt++)
#pragma unroll
            for (int j = 0; j < 4; j++) acc[mt][nt][j] = 0.0f;

    int buf = 0;
    for (int k0 = 0; k0 < Ec; k0 += 64, buf ^= 1) {
        CP_WAIT0;
        __syncthreads();

        if (k0 + 64 < Ec) {
            int nb = buf ^ 1;
#pragma unroll
            for (int it = 0; it < 4; it++) {
                int i = tid + it * 256; int m = i >> 3; int ch = i & 7;
                cp16(smq + QKV_A(nb) + m * 144 + ch * 16,
                     xh + (size_t)(m0 + m) * Ec + k0 + 64 + ch * 8);
            }
#pragma unroll
            for (int it = 0; it < 6; it++) {
                int i = tid + it * 256; int row = i >> 3; int ch = i & 7;
                const __half* w = (row < 64) ? W0 : (row < 128) ? W1 : W2;
                cp16(smq + QKV_B(nb) + row * 144 + ch * 16,
                     w + (size_t)(row & 63) * Ec + k0 + 64 + ch * 8);
            }
            CP_COMMIT;
        }

        const unsigned* As = (const unsigned*)(smq + QKV_A(buf));
        const unsigned* Bs = (const unsigned*)(smq + QKV_B(buf));
#pragma unroll
        for (int kk = 0; kk < 4; kk++) {
            unsigned af[2][4];
#pragma unroll
            for (int mt = 0; mt < 2; mt++) {
                int R = wm * 32 + mt * 16;
                af[mt][0] = As[(R + r) * 36 + kk * 8 + c];
                af[mt][1] = As[(R + r + 8) * 36 + kk * 8 + c];
                af[mt][2] = As[(R + r) * 36 + kk * 8 + c + 4];
                af[mt][3] = As[(R + r + 8) * 36 + kk * 8 + c + 4];
            }
#pragma unroll
            for (int nt = 0; nt < 12; nt++) {
                int Cn = wn * 96 + nt * 8;
                unsigned b0 = Bs[(Cn + r) * 36 + kk * 8 + c];
                unsigned b1 = Bs[(Cn + r) * 36 + kk * 8 + c + 4];
#pragma unroll
                for (int mt = 0; mt < 2; mt++)
                    mma16(acc[mt][nt], af[mt], b0, b1);
            }
        }
    }

    // epilogue: +bias, fp16 round, scatter to [B,H,S,D]
    const int bI = m0 >> 11;
    const int sBase = m0 & 2047;
#pragma unroll
    for (int nt = 0; nt < 12; nt++) {
        int g   = wn * 96 + nt * 8;
        int mat = g >> 6;
        int d   = (g & 63) + 2 * c;
        __half* Out = (mat == 0) ? g_Qh : (mat == 1) ? g_Kh : g_Vh;
        const float* bias = (mat == 0) ? bq : (mat == 1) ? bk : bv;
        float bb0 = bias[h * Dc + d], bb1 = bias[h * Dc + d + 1];
#pragma unroll
        for (int mt = 0; mt < 2; mt++) {
            int lr = wm * 32 + mt * 16 + r;
            size_t base = ((((size_t)bI * Hc + h) * Sc) + sBase + lr) * Dc + d;
            *(unsigned*)(Out + base)          = pk(acc[mt][nt][0] + bb0, acc[mt][nt][1] + bb1);
            *(unsigned*)(Out + base + 8 * Dc) = pk(acc[mt][nt][2] + bb0, acc[mt][nt][3] + bb1);
        }
    }
}

// ---------------------------------------------------------------------------
// Kernel 3: output projection (fp16 HMMA k16). Block 128x128x64h, 8 warps
// (4m x 2n), warp tile 32x64. A = g_AOh, B = g_Wot. fp32 out.
// smem bytes: A0@0 A1@18432 | B0@36864 B1@55296 -> 73728 B
// ---------------------------------------------------------------------------
#define O_A(b) ((b) * 18432)
#define O_B(b) (36864 + (b) * 18432)
#define O_SMEM 73728

__global__ __launch_bounds__(256, 1) void out_fp16_kernel(
    const float* __restrict__ bo, float* __restrict__ outp)
{
    extern __shared__ __align__(16) char smo[];

    const __half* __restrict__ A = (const __half*)g_AOh;
    const __half* __restrict__ B = (const __half*)g_Wot;

    const int tid  = threadIdx.x;
    const int warp = tid >> 5, lane = tid & 31;
    const int wm = warp >> 1, wn = warp & 1;
    const int r = lane >> 2, c = lane & 3;
    const int m0 = blockIdx.y * 128;
    const int ncol0 = blockIdx.x * 128;

#pragma unroll
    for (int it = 0; it < 4; it++) {
        int i = tid + it * 256; int m = i >> 3; int ch = i & 7;
        cp16(smo + O_A(0) + m * 144 + ch * 16, A + (size_t)(m0 + m) * HDc + ch * 8);
    }
#pragma unroll
    for (int it = 0; it < 4; it++) {
        int i = tid + it * 256; int row = i >> 3; int ch = i & 7;
        cp16(smo + O_B(0) + row * 144 + ch * 16,
             B + (size_t)(ncol0 + row) * HDc + ch * 8);
    }
    CP_COMMIT;

    float acc[2][8][4];
#pragma unroll
    for (int mt = 0; mt < 2; mt++)
#pragma unroll
        for (int nt = 0; nt < 8; nt++)
#pragma unroll
            for (int j = 0; j < 4; j++) acc[mt][nt][j] = 0.0f;

    int buf = 0;
    for (int k0 = 0; k0 < HDc; k0 += 64, buf ^= 1) {
        CP_WAIT0;
        __syncthreads();

        if (k0 + 64 < HDc) {
            int nb = buf ^ 1;
#pragma unroll
            for (int it = 0; it < 4; it++) {
                int i = tid + it * 256; int m = i >> 3; int ch = i & 7;
                cp16(smo + O_A(nb) + m * 144 + ch * 16,
                     A + (size_t)(m0 + m) * HDc + k0 + 64 + ch * 8);
            }
#pragma unroll
            for (int it = 0; it < 4; it++) {
                int i = tid + it * 256; int row = i >> 3; int ch = i & 7;
                cp16(smo + O_B(nb) + row * 144 + ch * 16,
                     B + (size_t)(ncol0 + row) * HDc + k0 + 64 + ch * 8);
            }
            CP_COMMIT;
        }

        const unsigned* As = (const unsigned*)(smo + O_A(buf));
        const unsigned* Bs = (const unsigned*)(smo + O_B(buf));
#pragma unroll
        for (int kk = 0; kk < 4; kk++) {
            unsigned af[2][4];
#pragma unroll
            for (int mt = 0; mt < 2; mt++) {
                int R = wm * 32 + mt * 16;
                af[mt][0] = As[(R + r) * 36 + kk * 8 + c];
                af[mt][1] = As[(R + r + 8) * 36 + kk * 8 + c];
                af[mt][2] = As[(R + r) * 36 + kk * 8 + c + 4];
                af[mt][3] = As[(R + r + 8) * 36 + kk * 8 + c + 4];
            }
#pragma unroll
            for (int nt = 0; nt < 8; nt++) {
                int Cn = wn * 64 + nt * 8;
                unsigned b0 = Bs[(Cn + r) * 36 + kk * 8 + c];
                unsigned b1 = Bs[(Cn + r) * 36 + kk * 8 + c + 4];
#pragma unroll
                for (int mt = 0; mt < 2; mt++)
                    mma16(acc[mt][nt], af[mt], b0, b1);
            }
        }
    }

#pragma unroll
    for (int mt = 0; mt < 2; mt++) {
        int mrow = m0 + wm * 32 + mt * 16 + r;
#pragma unroll
        for (int nt = 0; nt < 8; nt++) {
            int d = ncol0 + wn * 64 + nt * 8 + 2 * c;
            float bb0 = bo[d], bb1 = bo[d + 1];
            *(float2*)(outp + (size_t)mrow * Ec + d) =
                make_float2(acc[mt][nt][0] + bb0, acc[mt][nt][1] + bb1);
            *(float2*)(outp + (size_t)(mrow + 8) * Ec + d) =
                make_float2(acc[mt][nt][2] + bb0, acc[mt][nt][3] + bb1);
        }
    }
}

// ---------------------------------------------------------------------------
// Kernel 2: flash attention, fp16 HMMA k16. BQ=128 (8 warps), BKT=64, occ 2.
// P held in registers (S C-fragment == PV A-fragment after half2 packing).
// V B-fragments via ldmatrix.x4.trans on [token][d] tile (no V transpose).
// smem bytes: K0@0 V0@9216 | K1@18432 V1@27648 -> 36864 B (Q staged @0 first)
// ---------------------------------------------------------------------------
#define F_SMEM 36864

__device__ __forceinline__ void stage_kv_h(char* s, int base,
                                           const __half* Kb, const __half* Vb,
                                           int k0, int tid)
{
#pragma unroll
    for (int it = 0; it < 2; it++) {
        int i = tid + it * 256;
        int row = i >> 3, ch = i & 7;
        cp16(s + base + row * 144 + ch * 16,        Kb + (size_t)(k0 + row) * Dc + ch * 8);
        cp16(s + base + 9216 + row * 144 + ch * 16, Vb + (size_t)(k0 + row) * Dc + ch * 8);
    }
}

__global__ __launch_bounds__(256, 2) void flash_fp16_kernel()
{
    extern __shared__ __align__(16) char smf[];
    const unsigned sb = (unsigned)__cvta_generic_to_shared(smf);

    const int bh = blockIdx.y;
    const int b  = bh >> 4, h = bh & 15;
    const int q0 = blockIdx.x * 128;

    const __half* __restrict__ Qb = g_Qh + (size_t)bh * Sc * Dc;
    const __half* __restrict__ Kb = g_Kh + (size_t)bh * Sc * Dc;
    const __half* __restrict__ Vb = g_Vh + (size_t)bh * Sc * Dc;

    const int tid  = threadIdx.x;
    const int warp = tid >> 5, lane = tid & 31;
    const int r = lane >> 2, c = lane & 3;

    // stage Q (128x64 halves) transiently at smem base, extract A-fragments
#pragma unroll
    for (int it = 0; it < 4; it++) {
        int i = tid + it * 256;
        int row = i >> 3, ch = i & 7;
        cp16(smf + row * 144 + ch * 16, Qb + (size_t)(q0 + row) * Dc + ch * 8);
    }
    CP_COMMIT; CP_WAIT0;
    __syncthreads();

    unsigned qf[4][4];
    {
        const unsigned* Q32 = (const unsigned*)smf;
        int R = warp * 16;
#pragma unroll
        for (int kk = 0; kk < 4; kk++) {
            qf[kk][0] = Q32[(R + r) * 36 + kk * 8 + c];
            qf[kk][1] = Q32[(R + r + 8) * 36 + kk * 8 + c];
            qf[kk][2] = Q32[(R + r) * 36 + kk * 8 + c + 4];
            qf[kk][3] = Q32[(R + r + 8) * 36 + kk * 8 + c + 4];
        }
    }
    __syncthreads();

    const int nkt = 2 * (blockIdx.x + 1);
    stage_kv_h(smf, 0, Kb, Vb, 0, tid);
    CP_COMMIT;

    float of[8][4];
#pragma unroll
    for (int nt = 0; nt < 8; nt++)
#pragma unroll
        for (int j = 0; j < 4; j++) of[nt][j] = 0.0f;
    float m_lo = -1e30f, m_hi = -1e30f, l_lo = 0.0f, l_hi = 0.0f;

    const int qlo = q0 + warp * 16 + r;
    const int qhi = qlo + 8;
    const int qmax = q0 + warp * 16 + 15;

    const int lm = lane >> 3, lr8 = lane & 7;   // ldmatrix lane roles

    int buf = 0;
    for (int kt = 0; kt < nkt; kt++) {
        CP_WAIT0;
        __syncthreads();
        if (kt + 1 < nkt) {
            stage_kv_h(smf, (buf ^ 1) * 18432, Kb, Vb, (kt + 1) * 64, tid);
            CP_COMMIT;
        }
        const int kbase = kt * 64;
        if (kbase <= qmax) {
            const unsigned* K32 = (const unsigned*)(smf + buf * 18432);
            const unsigned vbase = sb + buf * 18432 + 9216;

            // S = Q K^T
            float sf[8][4];
#pragma unroll
            for (int nt = 0; nt < 8; nt++)
                sf[nt][0] = sf[nt][1] = sf[nt][2] = sf[nt][3] = 0.0f;
#pragma unroll
            for (int kk = 0; kk < 4; kk++) {
#pragma unroll
                for (int nt = 0; nt < 8; nt++) {
                    unsigned b0 = K32[(nt * 8 + r) * 36 + kk * 8 + c];
                    unsigned b1 = K32[(nt * 8 + r) * 36 + kk * 8 + c + 4];
                    mma16(sf[nt], qf[kk], b0, b1);
                }
            }

            // scale + causal mask + online softmax
            float mx_lo = -1e30f, mx_hi = -1e30f;
#pragma unroll
            for (int nt = 0; nt < 8; nt++) {
                int kg0 = kbase + nt * 8 + 2 * c;
                int kg1 = kg0 + 1;
                float s0 = sf[nt][0] * 0.125f; if (kg0 > qlo) s0 = -1e30f;
                float s1 = sf[nt][1] * 0.125f; if (kg1 > qlo) s1 = -1e30f;
                float s2 = sf[nt][2] * 0.125f; if (kg0 > qhi) s2 = -1e30f;
                float s3 = sf[nt][3] * 0.125f; if (kg1 > qhi) s3 = -1e30f;
                sf[nt][0] = s0; sf[nt][1] = s1; sf[nt][2] = s2; sf[nt][3] = s3;
                mx_lo = fmaxf(mx_lo, fmaxf(s0, s1));
                mx_hi = fmaxf(mx_hi, fmaxf(s2, s3));
            }
            mx_lo = fmaxf(mx_lo, __shfl_xor_sync(0xffffffffu, mx_lo, 1));
            mx_lo = fmaxf(mx_lo, __shfl_xor_sync(0xffffffffu, mx_lo, 2));
            mx_hi = fmaxf(mx_hi, __shfl_xor_sync(0xffffffffu, mx_hi, 1));
            mx_hi = fmaxf(mx_hi, __shfl_xor_sync(0xffffffffu, mx_hi, 2));

            float mn_lo = fmaxf(m_lo, mx_lo), mn_hi = fmaxf(m_hi, mx_hi);
            float a_lo = __expf(m_lo - mn_lo), a_hi = __expf(m_hi - mn_hi);

            unsigned pr0[8], pr1[8];
            float ps_lo = 0.0f, ps_hi = 0.0f;
#pragma unroll
            for (int nt = 0; nt < 8; nt++) {
                float p0 = __expf(sf[nt][0] - mn_lo);
                float p1 = __expf(sf[nt][1] - mn_lo);
                float p2 = __expf(sf[nt][2] - mn_hi);
                float p3 = __expf(sf[nt][3] - mn_hi);
                ps_lo += p0 + p1;  ps_hi += p2 + p3;
                pr0[nt] = pk(p0, p1);    // row r,   cols 2c,2c+1
                pr1[nt] = pk(p2, p3);    // row r+8
            }
            ps_lo += __shfl_xor_sync(0xffffffffu, ps_lo, 1);
            ps_lo += __shfl_xor_sync(0xffffffffu, ps_lo, 2);
            ps_hi += __shfl_xor_sync(0xffffffffu, ps_hi, 1);
            ps_hi += __shfl_xor_sync(0xffffffffu, ps_hi, 2);
            l_lo = l_lo * a_lo + ps_lo;
            l_hi = l_hi * a_hi + ps_hi;
            m_lo = mn_lo; m_hi = mn_hi;

#pragma unroll
            for (int nt = 0; nt < 8; nt++) {
                of[nt][0] *= a_lo; of[nt][1] *= a_lo;
                of[nt][2] *= a_hi; of[nt][3] *= a_hi;
            }

            // O += P V   (P in regs; V B-frags via ldmatrix.trans)
#pragma unroll
            for (int kk = 0; kk < 4; kk++) {
                unsigned pa[4] = { pr0[2 * kk], pr1[2 * kk],
                                   pr0[2 * kk + 1], pr1[2 * kk + 1] };
#pragma unroll
                for (int ntp = 0; ntp < 4; ntp++) {
                    unsigned vf[4];
                    unsigned va = vbase
                        + (unsigned)((kk * 16 + (lm & 1) * 8 + lr8) * 144)
                        + (unsigned)((ntp * 16 + (lm >> 1) * 8) * 2);
                    ldsm4t(vf, va);
                    mma16(of[2 * ntp],     pa, vf[0], vf[1]);
                    mma16(of[2 * ntp + 1], pa, vf[2], vf[3]);
                }
            }
        }
        buf ^= 1;
    }

    // epilogue: normalize, fp16 round, write AO [B,S,H*D]
    float il_lo = 1.0f / l_lo, il_hi = 1.0f / l_hi;
    size_t rb_lo = ((size_t)b * Sc + qlo) * HDc + h * Dc;
    size_t rb_hi = ((size_t)b * Sc + qhi) * HDc + h * Dc;
#pragma unroll
    for (int nt = 0; nt < 8; nt++) {
        int d = nt * 8 + 2 * c;
        *(unsigned*)(g_AOh + rb_lo + d) = pk(of[nt][0] * il_lo, of[nt][1] * il_lo);
        *(unsigned*)(g_AOh + rb_hi + d) = pk(of[nt][2] * il_hi, of[nt][3] * il_hi);
    }
}

// ---------------------------------------------------------------------------
extern "C" void kernel_launch(void* const* d_in, const int* in_sizes, int n_in,
                              void* d_out, int out_size)
{
    const float* x  = (const float*)d_in[0];
    const float* Wq = (const float*)d_in[1];
    const float* bq = (const float*)d_in[2];
    const float* Wk = (const float*)d_in[3];
    const float* bk = (const float*)d_in[4];
    const float* Wv = (const float*)d_in[5];
    const float* bv = (const float*)d_in[6];
    const float* Wo = (const float*)d_in[7];
    const float* bo = (const float*)d_in[8];
    float* out = (float*)d_out;

    cudaFuncSetAttribute(qkv_fp16_kernel,
                         cudaFuncAttributeMaxDynamicSharedMemorySize, QKV_SMEM);
    cudaFuncSetAttribute(flash_fp16_kernel,
                         cudaFuncAttributeMaxDynamicSharedMemorySize, F_SMEM);
    cudaFuncSetAttribute(out_fp16_kernel,
                         cudaFuncAttributeMaxDynamicSharedMemorySize, O_SMEM);

    round_x_kernel<<<1024, 256>>>(x);
    transpose_half_kernel<0><<<dim3(Dc / 32, Ec / 32, Hc), 256>>>(Wq);
    transpose_half_kernel<1><<<dim3(Dc / 32, Ec / 32, Hc), 256>>>(Wk);
    transpose_half_kernel<2><<<dim3(Dc / 32, Ec / 32, Hc), 256>>>(Wv);
    transpose_half_kernel<3><<<dim3(Ec / 32, HDc / 32, 1), 256>>>(Wo);

    dim3 g1(Mc / 128, Hc);
    qkv_fp16_kernel<<<g1, 256, QKV_SMEM>>>(bq, bk, bv);

    dim3 g2(Sc / 128, Bc * Hc);
    flash_fp16_kernel<<<g2, 256, F_SMEM>>>();

    dim3 g3(Ec / 128, Mc / 128);
    out_fp16_kernel<<<g3, 256, O_SMEM>>>(bo, out);
}

// round 11
// speedup vs baseline: 1.8979x; 1.0021x over previous
#include <cuda_runtime.h>
#include <cuda_fp16.h>
#include <cstdint>

// Problem dims (fixed)
#define Bc  4
#define Sc  2048
#define Ec  1024
#define Hc  16
#define Dc  64
#define HDc (Hc * Dc)      // 1024
#define Mc  (Bc * Sc)      // 8192

// Scratch (fp16 pipeline)
__device__ __half g_Qh[Bc * Hc * Sc * Dc];
__device__ __half g_Kh[Bc * Hc * Sc * Dc];
__device__ __half g_Vh[Bc * Hc * Sc * Dc];
__device__ __half g_AOh[Bc * Sc * HDc];
__device__ __half g_xh [Mc * Ec];
__device__ __half g_Wqt[Hc * Dc * Ec];   // transposed [h][d][e]
__device__ __half g_Wkt[Hc * Dc * Ec];
__device__ __half g_Wvt[Hc * Dc * Ec];
__device__ __half g_Wot[Ec * HDc];       // transposed [n][k]

// ---------------------------------------------------------------------------
// helpers
// ---------------------------------------------------------------------------
__device__ __forceinline__ unsigned pk(float a, float b) {
    __half2 h = __floats2half2_rn(a, b);
    return *reinterpret_cast<unsigned*>(&h);
}

__device__ __forceinline__ void mma16(float* d, const unsigned* a, unsigned b0, unsigned b1) {
    asm volatile(
        "mma.sync.aligned.m16n8k16.row.col.f32.f16.f16.f32 "
        "{%0,%1,%2,%3}, {%4,%5,%6,%7}, {%8,%9}, {%0,%1,%2,%3};"
        : "+f"(d[0]), "+f"(d[1]), "+f"(d[2]), "+f"(d[3])
        : "r"(a[0]), "r"(a[1]), "r"(a[2]), "r"(a[3]), "r"(b0), "r"(b1));
}

__device__ __forceinline__ void ldsm4(unsigned* f, unsigned addr_bytes) {
    asm volatile("ldmatrix.sync.aligned.m8n8.x4.shared.b16 {%0,%1,%2,%3}, [%4];"
        : "=r"(f[0]), "=r"(f[1]), "=r"(f[2]), "=r"(f[3]) : "r"(addr_bytes));
}
__device__ __forceinline__ void ldsm4t(unsigned* f, unsigned addr_bytes) {
    asm volatile("ldmatrix.sync.aligned.m8n8.x4.trans.shared.b16 {%0,%1,%2,%3}, [%4];"
        : "=r"(f[0]), "=r"(f[1]), "=r"(f[2]), "=r"(f[3]) : "r"(addr_bytes));
}

__device__ __forceinline__ void cp16(void* smem, const void* g) {
    unsigned sa = (unsigned)__cvta_generic_to_shared(smem);
    asm volatile("cp.async.cg.shared.global [%0], [%1], 16;" :: "r"(sa), "l"(g));
}
#define CP_COMMIT asm volatile("cp.async.commit_group;")
#define CP_WAIT0  asm volatile("cp.async.wait_group 0;")

// ---------------------------------------------------------------------------
// Prepass A: x (fp32) -> g_xh (fp16)
// ---------------------------------------------------------------------------
__global__ __launch_bounds__(256) void round_x_kernel(const float* __restrict__ x)
{
    const float4* src = (const float4*)x;
    uint2* dst = (uint2*)g_xh;
    const int n4 = Mc * Ec / 4;
    for (int i = blockIdx.x * blockDim.x + threadIdx.x; i < n4;
         i += gridDim.x * blockDim.x) {
        float4 v = src[i];
        dst[i] = make_uint2(pk(v.x, v.y), pk(v.z, v.w));
    }
}

// ---------------------------------------------------------------------------
// Prepass B: batched tiled transpose + fp16 convert (weights).
// ---------------------------------------------------------------------------
template<int SEL>
__global__ __launch_bounds__(256) void transpose_half_kernel(const float* __restrict__ srcp)
{
    __shared__ float t[32][33];
    int R, C; __half* dst;
    if      (SEL == 0) { dst = g_Wqt; R = Ec;  C = Dc; }
    else if (SEL == 1) { dst = g_Wkt; R = Ec;  C = Dc; }
    else if (SEL == 2) { dst = g_Wvt; R = Ec;  C = Dc; }
    else               { dst = g_Wot; R = HDc; C = Ec; }

    size_t off = (size_t)blockIdx.z * R * C;
    const float* S = srcp + off;
    __half* D = dst + off;
    int c0 = blockIdx.x * 32, r0 = blockIdx.y * 32;
    int tx = threadIdx.x & 31, ty = threadIdx.x >> 5;
#pragma unroll
    for (int i = 0; i < 32; i += 8)
        t[ty + i][tx] = S[(size_t)(r0 + ty + i) * C + c0 + tx];
    __syncthreads();
#pragma unroll
    for (int i = 0; i < 32; i += 8)
        D[(size_t)(c0 + ty + i) * R + r0 + tx] = __float2half_rn(t[tx][ty + i]);
}

// ---------------------------------------------------------------------------
// Kernel 1: FUSED QKV projection (fp16 HMMA k16 + ldmatrix).
// Block 128(M) x 192(N = Q|K|V of one head) x 64(K halves). 256 thr = 8 warps
// (4m x 2n), warp tile 32x96. Rows 144 B (stride 36 u32): every 8-row
// ldmatrix phase hits 8 distinct 4-bank groups -> conflict-free.
// smem bytes: A0@0 A1@18432 | B0@36864 B1@64512  -> 92160 B
// ---------------------------------------------------------------------------
#define QKV_A(b) ((b) * 18432)
#define QKV_B(b) (36864 + (b) * 27648)
#define QKV_SMEM 92160

__global__ __launch_bounds__(256, 1) void qkv_fp16_kernel(
    const float* __restrict__ bq, const float* __restrict__ bk,
    const float* __restrict__ bv)
{
    extern __shared__ __align__(16) char smq[];
    const unsigned sb = (unsigned)__cvta_generic_to_shared(smq);

    const int tid  = threadIdx.x;
    const int warp = tid >> 5, lane = tid & 31;
    const int wm = warp >> 1, wn = warp & 1;
    const int r = lane >> 2, c = lane & 3;
    const int ln15 = lane & 15, lhiB = (lane >> 4) * 16;   // 16-byte half-select
    const int m0 = blockIdx.x * 128;
    const int h  = blockIdx.y;

    const __half* __restrict__ W0 = g_Wqt + (size_t)h * Dc * Ec;
    const __half* __restrict__ W1 = g_Wkt + (size_t)h * Dc * Ec;
    const __half* __restrict__ W2 = g_Wvt + (size_t)h * Dc * Ec;
    const __half* __restrict__ xh = g_xh;

    // stage tile 0
#pragma unroll
    for (int it = 0; it < 4; it++) {
        int i = tid + it * 256; int m = i >> 3; int ch = i & 7;
        cp16(smq + QKV_A(0) + m * 144 + ch * 16, xh + (size_t)(m0 + m) * Ec + ch * 8);
    }
#pragma unroll
    for (int it = 0; it < 6; it++) {
        int i = tid + it * 256; int row = i >> 3; int ch = i & 7;
        const __half* w = (row < 64) ? W0 : (row < 128) ? W1 : W2;
        cp16(smq + QKV_B(0) + row * 144 + ch * 16, w + (size_t)(row & 63) * Ec + ch * 8);
    }
    CP_COMMIT;

    float acc[2][12][4];
#pragma unroll
    for (int mt = 0; mt < 2; mt++)
#pragma unroll
        for (int nt = 0; nt < 12; nt++)
#pragma unroll
            for (int j = 0; j < 4; j++) acc[mt][nt][j] = 0.0f;

    const unsigned aOff = (unsigned)((wm * 32 + ln15) * 144) + lhiB;
    const unsigned bOff = (unsigned)((wn * 96 + ln15) * 144) + lhiB;

    int buf = 0;
    for (int k0 = 0; k0 < Ec; k0 += 64, buf ^= 1) {
        CP_WAIT0;
        __syncthreads();

        if (k0 + 64 < Ec) {
            int nb = buf ^ 1;
#pragma unroll
            for (int it = 0; it < 4; it++) {
                int i = tid + it * 256; int m = i >> 3; int ch = i & 7;
                cp16(smq + QKV_A(nb) + m * 144 + ch * 16,
                     xh + (size_t)(m0 + m) * Ec + k0 + 64 + ch * 8);
            }
#pragma unroll
            for (int it = 0; it < 6; it++) {
                int i = tid + it * 256; int row = i >> 3; int ch = i & 7;
                const __half* w = (row < 64) ? W0 : (row < 128) ? W1 : W2;
                cp16(smq + QKV_B(nb) + row * 144 + ch * 16,
                     w + (size_t)(row & 63) * Ec + k0 + 64 + ch * 8);
            }
            CP_COMMIT;
        }

        const unsigned aB = sb + QKV_A(buf) + aOff;
        const unsigned bB = sb + QKV_B(buf) + bOff;
#pragma unroll
        for (int kk = 0; kk < 4; kk++) {
            unsigned af[2][4], bf[6][4];
            ldsm4(af[0], aB + kk * 32);
            ldsm4(af[1], aB + 16 * 144 + kk * 32);
#pragma unroll
            for (int p = 0; p < 6; p++)
                ldsm4(bf[p], bB + p * 16 * 144 + kk * 32);
#pragma unroll
            for (int nt = 0; nt < 12; nt++) {
                unsigned b0 = bf[nt >> 1][nt & 1];
                unsigned b1 = bf[nt >> 1][2 + (nt & 1)];
#pragma unroll
                for (int mt = 0; mt < 2; mt++)
                    mma16(acc[mt][nt], af[mt], b0, b1);
            }
        }
    }

    // epilogue: +bias, fp16 round, scatter to [B,H,S,D]
    const int bI = m0 >> 11;
    const int sBase = m0 & 2047;
#pragma unroll
    for (int nt = 0; nt < 12; nt++) {
        int g   = wn * 96 + nt * 8;
        int mat = g >> 6;
        int d   = (g & 63) + 2 * c;
        __half* Out = (mat == 0) ? g_Qh : (mat == 1) ? g_Kh : g_Vh;
        const float* bias = (mat == 0) ? bq : (mat == 1) ? bk : bv;
        float bb0 = bias[h * Dc + d], bb1 = bias[h * Dc + d + 1];
#pragma unroll
        for (int mt = 0; mt < 2; mt++) {
            int lr = wm * 32 + mt * 16 + r;
            size_t base = ((((size_t)bI * Hc + h) * Sc) + sBase + lr) * Dc + d;
            *(unsigned*)(Out + base)          = pk(acc[mt][nt][0] + bb0, acc[mt][nt][1] + bb1);
            *(unsigned*)(Out + base + 8 * Dc) = pk(acc[mt][nt][2] + bb0, acc[mt][nt][3] + bb1);
        }
    }
}

// ---------------------------------------------------------------------------
// Kernel 3: output projection (fp16 HMMA k16 + ldmatrix). Block 128x128x64h,
// 8 warps (4m x 2n), warp tile 32x64. A = g_AOh, B = g_Wot. fp32 out.
// smem bytes: A0@0 A1@18432 | B0@36864 B1@55296 -> 73728 B
// ---------------------------------------------------------------------------
#define O_A(b) ((b) * 18432)
#define O_B(b) (36864 + (b) * 18432)
#define O_SMEM 73728

__global__ __launch_bounds__(256, 1) void out_fp16_kernel(
    const float* __restrict__ bo, float* __restrict__ outp)
{
    extern __shared__ __align__(16) char smo[];
    const unsigned sb = (unsigned)__cvta_generic_to_shared(smo);

    const __half* __restrict__ A = (const __half*)g_AOh;
    const __half* __restrict__ B = (const __half*)g_Wot;

    const int tid  = threadIdx.x;
    const int warp = tid >> 5, lane = tid & 31;
    const int wm = warp >> 1, wn = warp & 1;
    const int r = lane >> 2, c = lane & 3;
    const int ln15 = lane & 15, lhiB = (lane >> 4) * 16;
    const int m0 = blockIdx.y * 128;
    const int ncol0 = blockIdx.x * 128;

#pragma unroll
    for (int it = 0; it < 4; it++) {
        int i = tid + it * 256; int m = i >> 3; int ch = i & 7;
        cp16(smo + O_A(0) + m * 144 + ch * 16, A + (size_t)(m0 + m) * HDc + ch * 8);
    }
#pragma unroll
    for (int it = 0; it < 4; it++) {
        int i = tid + it * 256; int row = i >> 3; int ch = i & 7;
        cp16(smo + O_B(0) + row * 144 + ch * 16,
             B + (size_t)(ncol0 + row) * HDc + ch * 8);
    }
    CP_COMMIT;

    float acc[2][8][4];
#pragma unroll
    for (int mt = 0; mt < 2; mt++)
#pragma unroll
        for (int nt = 0; nt < 8; nt++)
#pragma unroll
            for (int j = 0; j < 4; j++) acc[mt][nt][j] = 0.0f;

    const unsigned aOff = (unsigned)((wm * 32 + ln15) * 144) + lhiB;
    const unsigned bOff = (unsigned)((wn * 64 + ln15) * 144) + lhiB;

    int buf = 0;
    for (int k0 = 0; k0 < HDc; k0 += 64, buf ^= 1) {
        CP_WAIT0;
        __syncthreads();

        if (k0 + 64 < HDc) {
            int nb = buf ^ 1;
#pragma unroll
            for (int it = 0; it < 4; it++) {
                int i = tid + it * 256; int m = i >> 3; int ch = i & 7;
                cp16(smo + O_A(nb) + m * 144 + ch * 16,
                     A + (size_t)(m0 + m) * HDc + k0 + 64 + ch * 8);
            }
#pragma unroll
            for (int it = 0; it < 4; it++) {
                int i = tid + it * 256; int row = i >> 3; int ch = i & 7;
                cp16(smo + O_B(nb) + row * 144 + ch * 16,
                     B + (size_t)(ncol0 + row) * HDc + k0 + 64 + ch * 8);
            }
            CP_COMMIT;
        }

        const unsigned aB = sb + O_A(buf) + aOff;
        const unsigned bB = sb + O_B(buf) + bOff;
#pragma unroll
        for (int kk = 0; kk < 4; kk++) {
            unsigned af[2][4], bf[4][4];
            ldsm4(af[0], aB + kk * 32);
            ldsm4(af[1], aB + 16 * 144 + kk * 32);
#pragma unroll
            for (int p = 0; p < 4; p++)
                ldsm4(bf[p], bB + p * 16 * 144 + kk * 32);
#pragma unroll
            for (int nt = 0; nt < 8; nt++) {
                unsigned b0 = bf[nt >> 1][nt & 1];
                unsigned b1 = bf[nt >> 1][2 + (nt & 1)];
#pragma unroll
                for (int mt = 0; mt < 2; mt++)
                    mma16(acc[mt][nt], af[mt], b0, b1);
            }
        }
    }

#pragma unroll
    for (int mt = 0; mt < 2; mt++) {
        int mrow = m0 + wm * 32 + mt * 16 + r;
#pragma unroll
        for (int nt = 0; nt < 8; nt++) {
            int d = ncol0 + wn * 64 + nt * 8 + 2 * c;
            float bb0 = bo[d], bb1 = bo[d + 1];
            *(float2*)(outp + (size_t)mrow * Ec + d) =
                make_float2(acc[mt][nt][0] + bb0, acc[mt][nt][1] + bb1);
            *(float2*)(outp + (size_t)(mrow + 8) * Ec + d) =
                make_float2(acc[mt][nt][2] + bb0, acc[mt][nt][3] + bb1);
        }
    }
}

// ---------------------------------------------------------------------------
// Kernel 2: flash attention, fp16 HMMA k16 + ldmatrix. BQ=128 (8 warps),
// BKT=64, occ 2. P in registers; K B-frags via ldmatrix.x4; V via
// ldmatrix.x4.trans. smem: K0@0 V0@9216 | K1@18432 V1@27648 -> 36864 B
// ---------------------------------------------------------------------------
#define F_SMEM 36864

__device__ __forceinline__ void stage_kv_h(char* s, int base,
                                           const __half* Kb, const __half* Vb,
                                           int k0, int tid)
{
#pragma unroll
    for (int it = 0; it < 2; it++) {
        int i = tid + it * 256;
        int row = i >> 3, ch = i & 7;
        cp16(s + base + row * 144 + ch * 16,        Kb + (size_t)(k0 + row) * Dc + ch * 8);
        cp16(s + base + 9216 + row * 144 + ch * 16, Vb + (size_t)(k0 + row) * Dc + ch * 8);
    }
}

__global__ __launch_bounds__(256, 2) void flash_fp16_kernel()
{
    extern __shared__ __align__(16) char smf[];
    const unsigned sb = (unsigned)__cvta_generic_to_shared(smf);

    const int bh = blockIdx.y;
    const int b  = bh >> 4, h = bh & 15;
    const int q0 = blockIdx.x * 128;

    const __half* __restrict__ Qb = g_Qh + (size_t)bh * Sc * Dc;
    const __half* __restrict__ Kb = g_Kh + (size_t)bh * Sc * Dc;
    const __half* __restrict__ Vb = g_Vh + (size_t)bh * Sc * Dc;

    const int tid  = threadIdx.x;
    const int warp = tid >> 5, lane = tid & 31;
    const int r = lane >> 2, c = lane & 3;
    const int ln15 = lane & 15, lhiB = (lane >> 4) * 16;

    // stage Q (128x64 halves) transiently, extract A-fragments via ldmatrix
#pragma unroll
    for (int it = 0; it < 4; it++) {
        int i = tid + it * 256;
        int row = i >> 3, ch = i & 7;
        cp16(smf + row * 144 + ch * 16, Qb + (size_t)(q0 + row) * Dc + ch * 8);
    }
    CP_COMMIT; CP_WAIT0;
    __syncthreads();

    unsigned qf[4][4];
    {
        const unsigned qB = sb + (unsigned)((warp * 16 + ln15) * 144) + lhiB;
#pragma unroll
        for (int kk = 0; kk < 4; kk++)
            ldsm4(qf[kk], qB + kk * 32);
    }
    __syncthreads();

    const int nkt = 2 * (blockIdx.x + 1);
    stage_kv_h(smf, 0, Kb, Vb, 0, tid);
    CP_COMMIT;

    float of[8][4];
#pragma unroll
    for (int nt = 0; nt < 8; nt++)
#pragma unroll
        for (int j = 0; j < 4; j++) of[nt][j] = 0.0f;
    float m_lo = -1e30f, m_hi = -1e30f, l_lo = 0.0f, l_hi = 0.0f;

    const int qlo = q0 + warp * 16 + r;
    const int qhi = qlo + 8;
    const int qmax = q0 + warp * 16 + 15;

    const int lm = lane >> 3, lr8 = lane & 7;   // ldmatrix.trans lane roles

    int buf = 0;
    for (int kt = 0; kt < nkt; kt++) {
        CP_WAIT0;
        __syncthreads();
        if (kt + 1 < nkt) {
            stage_kv_h(smf, (buf ^ 1) * 18432, Kb, Vb, (kt + 1) * 64, tid);
            CP_COMMIT;
        }
        const int kbase = kt * 64;
        if (kbase <= qmax) {
            const unsigned kB = sb + buf * 18432 + (unsigned)(ln15 * 144) + lhiB;
            const unsigned vbase = sb + buf * 18432 + 9216;

            // S = Q K^T  (K B-frags via ldmatrix.x4)
            float sf[8][4];
#pragma unroll
            for (int nt = 0; nt < 8; nt++)
                sf[nt][0] = sf[nt][1] = sf[nt][2] = sf[nt][3] = 0.0f;
#pragma unroll
            for (int kk = 0; kk < 4; kk++) {
                unsigned kf[4][4];
#pragma unroll
                for (int p = 0; p < 4; p++)
                    ldsm4(kf[p], kB + p * 16 * 144 + kk * 32);
#pragma unroll
                for (int nt = 0; nt < 8; nt++)
                    mma16(sf[nt], qf[kk], kf[nt >> 1][nt & 1], kf[nt >> 1][2 + (nt & 1)]);
            }

            // scale + causal mask + online softmax
            float mx_lo = -1e30f, mx_hi = -1e30f;
#pragma unroll
            for (int nt = 0; nt < 8; nt++) {
                int kg0 = kbase + nt * 8 + 2 * c;
                int kg1 = kg0 + 1;
                float s0 = sf[nt][0] * 0.125f; if (kg0 > qlo) s0 = -1e30f;
                float s1 = sf[nt][1] * 0.125f; if (kg1 > qlo) s1 = -1e30f;
                float s2 = sf[nt][2] * 0.125f; if (kg0 > qhi) s2 = -1e30f;
                float s3 = sf[nt][3] * 0.125f; if (kg1 > qhi) s3 = -1e30f;
                sf[nt][0] = s0; sf[nt][1] = s1; sf[nt][2] = s2; sf[nt][3] = s3;
                mx_lo = fmaxf(mx_lo, fmaxf(s0, s1));
                mx_hi = fmaxf(mx_hi, fmaxf(s2, s3));
            }
            mx_lo = fmaxf(mx_lo, __shfl_xor_sync(0xffffffffu, mx_lo, 1));
            mx_lo = fmaxf(mx_lo, __shfl_xor_sync(0xffffffffu, mx_lo, 2));
            mx_hi = fmaxf(mx_hi, __shfl_xor_sync(0xffffffffu, mx_hi, 1));
            mx_hi = fmaxf(mx_hi, __shfl_xor_sync(0xffffffffu, mx_hi, 2));

            float mn_lo = fmaxf(m_lo, mx_lo), mn_hi = fmaxf(m_hi, mx_hi);
            float a_lo = __expf(m_lo - mn_lo), a_hi = __expf(m_hi - mn_hi);

            unsigned pr0[8], pr1[8];
            float ps_lo = 0.0f, ps_hi = 0.0f;
#pragma unroll
            for (int nt = 0; nt < 8; nt++) {
                float p0 = __expf(sf[nt][0] - mn_lo);
                float p1 = __expf(sf[nt][1] - mn_lo);
                float p2 = __expf(sf[nt][2] - mn_hi);
                float p3 = __expf(sf[nt][3] - mn_hi);
                ps_lo += p0 + p1;  ps_hi += p2 + p3;
                pr0[nt] = pk(p0, p1);
                pr1[nt] = pk(p2, p3);
            }
            ps_lo += __shfl_xor_sync(0xffffffffu, ps_lo, 1);
            ps_lo += __shfl_xor_sync(0xffffffffu, ps_lo, 2);
            ps_hi += __shfl_xor_sync(0xffffffffu, ps_hi, 1);
            ps_hi += __shfl_xor_sync(0xffffffffu, ps_hi, 2);
            l_lo = l_lo * a_lo + ps_lo;
            l_hi = l_hi * a_hi + ps_hi;
            m_lo = mn_lo; m_hi = mn_hi;

#pragma unroll
            for (int nt = 0; nt < 8; nt++) {
                of[nt][0] *= a_lo; of[nt][1] *= a_lo;
                of[nt][2] *= a_hi; of[nt][3] *= a_hi;
            }

            // O += P V   (P in regs; V B-frags via ldmatrix.trans)
#pragma unroll
            for (int kk = 0; kk < 4; kk++) {
                unsigned pa[4] = { pr0[2 * kk], pr1[2 * kk],
                                   pr0[2 * kk + 1], pr1[2 * kk + 1] };
#pragma unroll
                for (int ntp = 0; ntp < 4; ntp++) {
                    unsigned vf[4];
                    unsigned va = vbase
                        + (unsigned)((kk * 16 + (lm & 1) * 8 + lr8) * 144)
                        + (unsigned)((ntp * 16 + (lm >> 1) * 8) * 2);
                    ldsm4t(vf, va);
                    mma16(of[2 * ntp],     pa, vf[0], vf[1]);
                    mma16(of[2 * ntp + 1], pa, vf[2], vf[3]);
                }
            }
        }
        buf ^= 1;
    }

    // epilogue: normalize, fp16 round, write AO [B,S,H*D]
    float il_lo = 1.0f / l_lo, il_hi = 1.0f / l_hi;
    size_t rb_lo = ((size_t)b * Sc + qlo) * HDc + h * Dc;
    size_t rb_hi = ((size_t)b * Sc + qhi) * HDc + h * Dc;
#pragma unroll
    for (int nt = 0; nt < 8; nt++) {
        int d = nt * 8 + 2 * c;
        *(unsigned*)(g_AOh + rb_lo + d) = pk(of[nt][0] * il_lo, of[nt][1] * il_lo);
        *(unsigned*)(g_AOh + rb_hi + d) = pk(of[nt][2] * il_hi, of[nt][3] * il_hi);
    }
}

// ---------------------------------------------------------------------------
extern "C" void kernel_launch(void* const* d_in, const int* in_sizes, int n_in,
                              void* d_out, int out_size)
{
    const float* x  = (const float*)d_in[0];
    const float* Wq = (const float*)d_in[1];
    const float* bq = (const float*)d_in[2];
    const float* Wk = (const float*)d_in[3];
    const float* bk = (const float*)d_in[4];
    const float* Wv = (const float*)d_in[5];
    const float* bv = (const float*)d_in[6];
    const float* Wo = (const float*)d_in[7];
    const float* bo = (const float*)d_in[8];
    float* out = (float*)d_out;

    cudaFuncSetAttribute(qkv_fp16_kernel,
                         cudaFuncAttributeMaxDynamicSharedMemorySize, QKV_SMEM);
    cudaFuncSetAttribute(flash_fp16_kernel,
                         cudaFuncAttributeMaxDynamicSharedMemorySize, F_SMEM);
    cudaFuncSetAttribute(out_fp16_kernel,
                         cudaFuncAttributeMaxDynamicSharedMemorySize, O_SMEM);

    round_x_kernel<<<1024, 256>>>(x);
    transpose_half_kernel<0><<<dim3(Dc / 32, Ec / 32, Hc), 256>>>(Wq);
    transpose_half_kernel<1><<<dim3(Dc / 32, Ec / 32, Hc), 256>>>(Wk);
    transpose_half_kernel<2><<<dim3(Dc / 32, Ec / 32, Hc), 256>>>(Wv);
    transpose_half_kernel<3><<<dim3(Ec / 32, HDc / 32, 1), 256>>>(Wo);

    dim3 g1(Mc / 128, Hc);
    qkv_fp16_kernel<<<g1, 256, QKV_SMEM>>>(bq, bk, bv);

    dim3 g2(Sc / 128, Bc * Hc);
    flash_fp16_kernel<<<g2, 256, F_SMEM>>>();

    dim3 g3(Ec / 128, Mc / 128);
    out_fp16_kernel<<<g3, 256, O_SMEM>>>(bo, out);
}